// round 11
// baseline (speedup 1.0000x reference)
#include <cuda_runtime.h>
#include <cuda_bf16.h>
#include <cstdint>

#define KNN 16
#define CIN 128
#define CPE 32
#define CF 160
#define CM 16
#define KDIM 2560
#define COUT 128
#define ND_MAX 40000

// split-bf16 scratch: S[n][k] with k = m*160+c ; B[n][k] = Wperm[k][n]
__device__ __nv_bfloat16 g_Shi[(size_t)ND_MAX * KDIM];
__device__ __nv_bfloat16 g_Slo[(size_t)ND_MAX * KDIM];
__device__ __nv_bfloat16 g_Bhi[(size_t)COUT * KDIM];
__device__ __nv_bfloat16 g_Blo[(size_t)COUT * KDIM];

// ---------------- common helpers ----------------
template<int N>
__device__ __forceinline__ void layer_norm(float* x, const float* g, const float* be, bool act){
    float s = 0.f;
#pragma unroll
    for (int i = 0; i < N; i++) s += x[i];
    float mu = s * (1.0f / N);
    float v = 0.f;
#pragma unroll
    for (int i = 0; i < N; i++){ float d = x[i] - mu; v += d * d; }
    float inv = rsqrtf(v * (1.0f / N) + 1e-5f);
#pragma unroll
    for (int i = 0; i < N; i++){
        float y = (x[i] - mu) * inv * g[i] + be[i];
        x[i] = act ? (y >= 0.f ? y : 0.1f * y) : y;
    }
}

__device__ __forceinline__ void dense16(const float* w, const float* bvec, const float* in, float* out){
#pragma unroll
    for (int o = 0; o < 16; o++) out[o] = bvec[o];
#pragma unroll
    for (int i = 0; i < 16; i++){
        float hi = in[i];
#pragma unroll
        for (int o4 = 0; o4 < 4; o4++){
            float4 ww = *(const float4*)&w[i*16 + o4*4];
            out[o4*4+0] = fmaf(hi, ww.x, out[o4*4+0]);
            out[o4*4+1] = fmaf(hi, ww.y, out[o4*4+1]);
            out[o4*4+2] = fmaf(hi, ww.z, out[o4*4+2]);
            out[o4*4+3] = fmaf(hi, ww.w, out[o4*4+3]);
        }
    }
}

__device__ __forceinline__ uint32_t s2u(const void* p){
    uint32_t a; asm("{ .reg .u64 t; cvta.to.shared.u64 t, %1; cvt.u32.u64 %0, t; }" : "=r"(a) : "l"(p));
    return a;
}
__device__ __forceinline__ void cpa16(uint32_t dst, const void* src){
    asm volatile("cp.async.cg.shared.global [%0], [%1], 16;" :: "r"(dst), "l"(src));
}

enum {
    PE_W0 = 0,    PE_B0 = 96,   PE_G0 = 128,  PE_BE0 = 160,
    PE_W1 = 192,  PE_B1 = 1216, PE_G1 = 1248, PE_BE1 = 1280,
    WN_W0 = 1312, WN_B0 = 1360, WN_G0 = 1376, WN_BE0 = 1392,
    WN_W1 = 1408, WN_B1 = 1664, WN_G1 = 1680, WN_BE1 = 1696,
    WN_W2 = 1712, WN_B2 = 1968, WN_G2 = 1984, WN_BE2 = 2000,
    P_TOTAL = 2016
};

#define PTS 8

// ===================== Kernel 1 (round-9): gather(cp.async dbuf) + MLPs + einsum =====================
__global__ __launch_bounds__(128)
void k1_weights_einsum(
    const float* __restrict__ sxyz,  const float* __restrict__ sfeat,
    const int*   __restrict__ nei,   const float* __restrict__ dxyz,
    const float* __restrict__ pw0, const float* __restrict__ pb0,
    const float* __restrict__ pg0, const float* __restrict__ pe0,
    const float* __restrict__ pw1, const float* __restrict__ pb1,
    const float* __restrict__ pg1, const float* __restrict__ pe1,
    const float* __restrict__ ww0, const float* __restrict__ wb0,
    const float* __restrict__ wg0, const float* __restrict__ we0,
    const float* __restrict__ ww1, const float* __restrict__ wb1,
    const float* __restrict__ wg1, const float* __restrict__ we1,
    const float* __restrict__ ww2, const float* __restrict__ wb2,
    const float* __restrict__ wg2, const float* __restrict__ we2,
    int Nd)
{
    __shared__ __align__(16) float sp[P_TOTAL];
    __shared__ __align__(16) float pe_s[PTS][KNN][CPE];
    __shared__ __align__(16) float wts_s[PTS][KNN][CM];
    __shared__ __align__(16) float feat_s[2][KNN][132];
    __shared__ int nei_s[PTS][KNN];

    const int t = threadIdx.x;
#define CPY(off, src, n) for (int i = t; i < (n); i += 128) sp[(off)+i] = (src)[i];
    CPY(PE_W0, pw0, 96)   CPY(PE_B0, pb0, 32)  CPY(PE_G0, pg0, 32)  CPY(PE_BE0, pe0, 32)
    CPY(PE_W1, pw1, 1024) CPY(PE_B1, pb1, 32)  CPY(PE_G1, pg1, 32)  CPY(PE_BE1, pe1, 32)
    CPY(WN_W0, ww0, 48)   CPY(WN_B0, wb0, 16)  CPY(WN_G0, wg0, 16)  CPY(WN_BE0, we0, 16)
    CPY(WN_W1, ww1, 256)  CPY(WN_B1, wb1, 16)  CPY(WN_G1, wg1, 16)  CPY(WN_BE1, we1, 16)
    CPY(WN_W2, ww2, 256)  CPY(WN_B2, wb2, 16)  CPY(WN_G2, wg2, 16)  CPY(WN_BE2, we2, 16)
#undef CPY
    __syncthreads();

    const int n0 = blockIdx.x * PTS;

    // ---- phase 1: one (point, neighbor) per thread ----
    {
        const int p = t >> 4, k = t & 15;
        int n = n0 + p; if (n >= Nd) n = Nd - 1;
        const int idx = nei[n * KNN + k];
        nei_s[p][k] = idx;
        const float x0 = sxyz[idx*3+0] - dxyz[n*3+0];
        const float x1 = sxyz[idx*3+1] - dxyz[n*3+1];
        const float x2 = sxyz[idx*3+2] - dxyz[n*3+2];

        float h[32];
#pragma unroll
        for (int o = 0; o < 32; o++)
            h[o] = fmaf(x0, sp[PE_W0+o], fmaf(x1, sp[PE_W0+32+o], fmaf(x2, sp[PE_W0+64+o], sp[PE_B0+o])));
        layer_norm<32>(h, &sp[PE_G0], &sp[PE_BE0], true);

        float h2[32];
#pragma unroll
        for (int o = 0; o < 32; o++) h2[o] = sp[PE_B1+o];
#pragma unroll
        for (int i = 0; i < 32; i++){
            float hi = h[i];
#pragma unroll
            for (int o4 = 0; o4 < 8; o4++){
                float4 ww = *(const float4*)&sp[PE_W1 + i*32 + o4*4];
                h2[o4*4+0] = fmaf(hi, ww.x, h2[o4*4+0]);
                h2[o4*4+1] = fmaf(hi, ww.y, h2[o4*4+1]);
                h2[o4*4+2] = fmaf(hi, ww.z, h2[o4*4+2]);
                h2[o4*4+3] = fmaf(hi, ww.w, h2[o4*4+3]);
            }
        }
        layer_norm<32>(h2, &sp[PE_G1], &sp[PE_BE1], false);
#pragma unroll
        for (int o = 0; o < 32; o++) pe_s[p][k][o] = h2[o];

        float u[16];
#pragma unroll
        for (int o = 0; o < 16; o++)
            u[o] = fmaf(x0, sp[WN_W0+o], fmaf(x1, sp[WN_W0+16+o], fmaf(x2, sp[WN_W0+32+o], sp[WN_B0+o])));
        layer_norm<16>(u, &sp[WN_G0], &sp[WN_BE0], true);
        float u2[16];
        dense16(&sp[WN_W1], &sp[WN_B1], u, u2);
        layer_norm<16>(u2, &sp[WN_G1], &sp[WN_BE1], true);
        float u3[16];
        dense16(&sp[WN_W2], &sp[WN_B2], u2, u3);
        layer_norm<16>(u3, &sp[WN_G2], &sp[WN_BE2], false);
#pragma unroll
        for (int o = 0; o < 16; o++) wts_s[p][k][o] = u3[o];
    }
    __syncthreads();

    // ---- phase 2: cp.async double-buffered gather overlapped with einsum ----
    const int gk = t >> 3, gq = t & 7;
    const uint32_t fbase = s2u(&feat_s[0][0][0]);
    const uint32_t frow  = (uint32_t)(gk * 132 * 4 + gq * 16);
    const uint32_t fbuf  = (uint32_t)(KNN * 132 * 4);

    {
        const float* src = sfeat + (size_t)nei_s[0][gk] * CIN + gq*4;
#pragma unroll
        for (int r = 0; r < 4; r++)
            cpa16(fbase + frow + r*128, src + 32*r);
        asm volatile("cp.async.commit_group;");
    }

    for (int p = 0; p < PTS; p++){
        const int n = n0 + p;
        if (p + 1 < PTS){
            const float* src = sfeat + (size_t)nei_s[p+1][gk] * CIN + gq*4;
            const uint32_t dst = fbase + ((p+1) & 1) * fbuf + frow;
#pragma unroll
            for (int r = 0; r < 4; r++)
                cpa16(dst + r*128, src + 32*r);
            asm volatile("cp.async.commit_group;");
            asm volatile("cp.async.wait_group 1;");
        } else {
            asm volatile("cp.async.wait_group 0;");
        }
        __syncthreads();

        if (n < Nd){
            const int cg = t & 31, mg = t >> 5;
            const float (*fs)[132] = feat_s[p & 1];
            float acc[5][4];
#pragma unroll
            for (int j = 0; j < 5; j++)
#pragma unroll
                for (int i = 0; i < 4; i++) acc[j][i] = 0.f;
#pragma unroll
            for (int k = 0; k < KNN; k++){
                float4 w = *(const float4*)&wts_s[p][k][mg*4];
#pragma unroll
                for (int j = 0; j < 5; j++){
                    float f = (j < 4) ? fs[k][cg + 32*j] : pe_s[p][k][cg];
                    acc[j][0] = fmaf(f, w.x, acc[j][0]);
                    acc[j][1] = fmaf(f, w.y, acc[j][1]);
                    acc[j][2] = fmaf(f, w.z, acc[j][2]);
                    acc[j][3] = fmaf(f, w.w, acc[j][3]);
                }
            }
            __nv_bfloat16* oh = g_Shi + (size_t)n * KDIM;
            __nv_bfloat16* ol = g_Slo + (size_t)n * KDIM;
#pragma unroll
            for (int i = 0; i < 4; i++)
#pragma unroll
                for (int j = 0; j < 5; j++){
                    float x = acc[j][i];
                    int idx = (mg*4 + i)*CF + cg + 32*j;
                    __nv_bfloat16 hi = __float2bfloat16_rn(x);
                    oh[idx] = hi;
                    ol[idx] = __float2bfloat16_rn(x - __bfloat162float(hi));
                }
        }
        __syncthreads();
    }
}

// ===================== prep: permute + split lin_w into B[n][k] =====================
__global__ __launch_bounds__(256)
void kprep(const float* __restrict__ W)
{
    int id = blockIdx.x * 256 + threadIdx.x;
    if (id >= COUT * KDIM) return;
    int n = id / KDIM, k = id - n * KDIM;
    int c = k % CF, m = k / CF;
    float x = W[(long)(c * CM + m) * COUT + n];
    __nv_bfloat16 hi = __float2bfloat16_rn(x);
    g_Bhi[id] = hi;
    g_Blo[id] = __float2bfloat16_rn(x - __bfloat162float(hi));
}

// ===================== Kernel 2: merged single-pass bf16-split GEMM + LN epilogue =====================
// BM=128, BN=128, BK=32; 256 threads, warp grid 4(m) x 2(n), warp tile 32x64.
// Per chunk: load Ahi, Alo, Bh, Bl; issue Ahi*Bh + Ahi*Bl + Alo*Bh (96 MMAs/warp per barrier).
#define BK 32
#define NCH (KDIM / BK)        // 80
#define APITCH 40              // bf16 per smem row (80 B) -> conflict-free ldmatrix
#define A_BYTES (128 * APITCH * 2)   // 10240
#define B_BYTES (128 * APITCH * 2)   // 10240
// stage layout: [Ahi | Alo | Bh | Bl]
#define OFF_ALO A_BYTES
#define OFF_BH  (2 * A_BYTES)
#define OFF_BL  (2 * A_BYTES + B_BYTES)
#define STG (2 * A_BYTES + 2 * B_BYTES)  // 40960
#define DSMEM (2 * STG)                  // 81920 (epilogue tile 128*132*4 = 67584 fits)

__device__ __forceinline__ void ldm4(uint32_t* r, uint32_t a){
    asm volatile("ldmatrix.sync.aligned.m8n8.x4.shared.b16 {%0,%1,%2,%3}, [%4];"
        : "=r"(r[0]), "=r"(r[1]), "=r"(r[2]), "=r"(r[3]) : "r"(a));
}
__device__ __forceinline__ void mma16816(float* d, const uint32_t* a, const uint32_t* b){
    asm volatile("mma.sync.aligned.m16n8k16.row.col.f32.bf16.bf16.f32 "
        "{%0,%1,%2,%3}, {%4,%5,%6,%7}, {%8,%9}, {%0,%1,%2,%3};"
        : "+f"(d[0]), "+f"(d[1]), "+f"(d[2]), "+f"(d[3])
        : "r"(a[0]), "r"(a[1]), "r"(a[2]), "r"(a[3]), "r"(b[0]), "r"(b[1]));
}

__device__ __forceinline__ void load_chunk(uint32_t base, int row0, int kb, int t, int Nd)
{
#pragma unroll
    for (int i = 0; i < 2; i++){
        int f = t + 256*i; int r = f >> 2, sg = f & 3;
        int rr = row0 + r; if (rr >= Nd) rr = Nd - 1;
        cpa16(base + r*80 + sg*16,           g_Shi + (size_t)rr * KDIM + kb + sg*8);
        cpa16(base + OFF_ALO + r*80 + sg*16, g_Slo + (size_t)rr * KDIM + kb + sg*8);
    }
#pragma unroll
    for (int i = 0; i < 2; i++){
        int f = t + 256*i; int r = f >> 2, sg = f & 3;
        cpa16(base + OFF_BH + r*80 + sg*16, g_Bhi + (size_t)r * KDIM + kb + sg*8);
        cpa16(base + OFF_BL + r*80 + sg*16, g_Blo + (size_t)r * KDIM + kb + sg*8);
    }
}

__global__ __launch_bounds__(256, 2)
void k2_gemm_ln(const float* __restrict__ lb, const float* __restrict__ lg,
                const float* __restrict__ lbe, const float* __restrict__ dfeat,
                float* __restrict__ out, int Nd)
{
    extern __shared__ __align__(128) char dsm[];
    __shared__ float sb[COUT], sg_[COUT], sbe[COUT];
    __shared__ float red[128][2][2];

    const int t = threadIdx.x;
    const int w = t >> 5, l = t & 31;
    const int wm = w & 3, wn = w >> 2;
    const int row0 = blockIdx.x * 128;

    for (int i = t; i < COUT; i += 256){ sb[i] = lb[i]; sg_[i] = lg[i]; sbe[i] = lbe[i]; }

    const uint32_t smem = s2u(dsm);
    const int grp = l >> 3, lr = l & 7;
    const int aRow = wm*32 + ((grp & 1) << 3) + lr;
    const int aK   = (grp >> 1) << 3;
    const int bRow = wn*64 + ((grp >> 1) << 3) + lr;
    const int bK   = (grp & 1) << 3;

    float acc[2][8][4];
#pragma unroll
    for (int i = 0; i < 2; i++)
#pragma unroll
        for (int j = 0; j < 8; j++)
#pragma unroll
            for (int q = 0; q < 4; q++) acc[i][j][q] = 0.f;

    __syncthreads();

    load_chunk(smem, row0, 0, t, Nd);
    asm volatile("cp.async.commit_group;");
    for (int ch = 0; ch < NCH; ch++){
        const uint32_t cur = smem + (ch & 1) * STG;
        if (ch + 1 < NCH){
            load_chunk(smem + ((ch + 1) & 1) * STG, row0, (ch + 1) * BK, t, Nd);
            asm volatile("cp.async.commit_group;");
            asm volatile("cp.async.wait_group 1;");
        } else {
            asm volatile("cp.async.wait_group 0;");
        }
        __syncthreads();
#pragma unroll
        for (int s = 0; s < 2; s++){
            uint32_t ah[2][4], al[2][4];
#pragma unroll
            for (int i = 0; i < 2; i++){
                ldm4(ah[i], cur + (uint32_t)((aRow + i*16)*80 + (s*16 + aK)*2));
                ldm4(al[i], cur + OFF_ALO + (uint32_t)((aRow + i*16)*80 + (s*16 + aK)*2));
            }
            uint32_t bh[4][4], bl[4][4];
#pragma unroll
            for (int j2 = 0; j2 < 4; j2++){
                ldm4(bh[j2], cur + OFF_BH + (uint32_t)((bRow + j2*16)*80 + (s*16 + bK)*2));
                ldm4(bl[j2], cur + OFF_BL + (uint32_t)((bRow + j2*16)*80 + (s*16 + bK)*2));
            }
#pragma unroll
            for (int i = 0; i < 2; i++)
#pragma unroll
                for (int j2 = 0; j2 < 4; j2++){
                    mma16816(acc[i][2*j2],   ah[i], &bh[j2][0]);
                    mma16816(acc[i][2*j2+1], ah[i], &bh[j2][2]);
                    mma16816(acc[i][2*j2],   ah[i], &bl[j2][0]);
                    mma16816(acc[i][2*j2+1], ah[i], &bl[j2][2]);
                    mma16816(acc[i][2*j2],   al[i], &bh[j2][0]);
                    mma16816(acc[i][2*j2+1], al[i], &bh[j2][2]);
                }
        }
        __syncthreads();
    }

    // ---- epilogue: acc -> smem (with bias), row LN + lrelu + residual ----
    float* sm = (float*)dsm;   // [128][132]
    const int P = 132;
    const int dr = l >> 2, dc = 2 * (l & 3);
#pragma unroll
    for (int i = 0; i < 2; i++)
#pragma unroll
        for (int j = 0; j < 8; j++){
            int row = wm*32 + i*16 + dr;
            int col = wn*64 + j*8 + dc;
            sm[row*P + col]         = acc[i][j][0] + sb[col];
            sm[row*P + col + 1]     = acc[i][j][1] + sb[col + 1];
            sm[(row+8)*P + col]     = acc[i][j][2] + sb[col];
            sm[(row+8)*P + col + 1] = acc[i][j][3] + sb[col + 1];
        }
    __syncthreads();

    {   // stats: thread t handles row t>>1, half t&1
        const int r = t >> 1, h = t & 1;
        float s = 0.f, ss = 0.f;
#pragma unroll 16
        for (int c = 0; c < 64; c++){
            float v = sm[r*P + h*64 + c];
            s += v; ss += v * v;
        }
        red[r][h][0] = s; red[r][h][1] = ss;
    }
    __syncthreads();

    // write out: warp w -> rows w*16 .. w*16+15, lane l -> cols l*4..l*4+3
    for (int rr = 0; rr < 16; rr++){
        const int row = w*16 + rr;
        const int gr = row0 + row;
        if (gr >= Nd) continue;
        const float S  = red[row][0][0] + red[row][1][0];
        const float SS = red[row][0][1] + red[row][1][1];
        const float mu  = S * (1.0f / 128.0f);
        const float var = SS * (1.0f / 128.0f) - mu * mu;
        const float inv = rsqrtf(var + 1e-5f);
        const int c0 = l * 4;
        float4 d = *(const float4*)&dfeat[(size_t)gr * COUT + c0];
        float o[4];
#pragma unroll
        for (int q = 0; q < 4; q++){
            float y = (sm[row*P + c0 + q] - mu) * inv * sg_[c0 + q] + sbe[c0 + q];
            o[q] = (y >= 0.f) ? y : 0.1f * y;
        }
        o[0] += d.x; o[1] += d.y; o[2] += d.z; o[3] += d.w;
        *(float4*)&out[(size_t)gr * COUT + c0] = make_float4(o[0], o[1], o[2], o[3]);
    }
}

// ============================================================================
extern "C" void kernel_launch(void* const* d_in, const int* in_sizes, int n_in,
                              void* d_out, int out_size)
{
    const float* sxyz  = (const float*)d_in[0];
    const float* sfeat = (const float*)d_in[1];
    const int*   nei   = (const int*)  d_in[2];
    const float* dxyz  = (const float*)d_in[4];
    const float* dfeat = (const float*)d_in[6];
    const float* pw0 = (const float*)d_in[7],  *pb0 = (const float*)d_in[8];
    const float* pg0 = (const float*)d_in[9],  *pe0 = (const float*)d_in[10];
    const float* pw1 = (const float*)d_in[11], *pb1 = (const float*)d_in[12];
    const float* pg1 = (const float*)d_in[13], *pe1 = (const float*)d_in[14];
    const float* ww0 = (const float*)d_in[15], *wb0 = (const float*)d_in[16];
    const float* wg0 = (const float*)d_in[17], *we0 = (const float*)d_in[18];
    const float* ww1 = (const float*)d_in[19], *wb1 = (const float*)d_in[20];
    const float* wg1 = (const float*)d_in[21], *we1 = (const float*)d_in[22];
    const float* ww2 = (const float*)d_in[23], *wb2 = (const float*)d_in[24];
    const float* wg2 = (const float*)d_in[25], *we2 = (const float*)d_in[26];
    const float* lw  = (const float*)d_in[27], *lb  = (const float*)d_in[28];
    const float* lg  = (const float*)d_in[29], *lbe = (const float*)d_in[30];
    float* out = (float*)d_out;

    const int Nd = in_sizes[4] / 3;   // 40000

    cudaFuncSetAttribute(k2_gemm_ln, cudaFuncAttributeMaxDynamicSharedMemorySize, DSMEM);

    kprep<<<(COUT * KDIM + 255) / 256, 256>>>(lw);

    k1_weights_einsum<<<(Nd + PTS - 1) / PTS, 128>>>(
        sxyz, sfeat, nei, dxyz,
        pw0, pb0, pg0, pe0, pw1, pb1, pg1, pe1,
        ww0, wb0, wg0, we0, ww1, wb1, wg1, we1, ww2, wb2, wg2, we2, Nd);

    k2_gemm_ln<<<(Nd + 127) / 128, 256, DSMEM>>>(lb, lg, lbe, dfeat, out, Nd);
}

// round 12
// speedup vs baseline: 1.1627x; 1.1627x over previous
#include <cuda_runtime.h>
#include <cuda_bf16.h>
#include <cstdint>

#define KNN 16
#define CIN 128
#define CPE 32
#define CF 160
#define CM 16
#define KDIM 2560
#define COUT 128
#define ND_MAX 40000

// split-bf16 scratch: S[n][k] with k = m*160+c ; B[n][k] = Wperm[k][n]
__device__ __nv_bfloat16 g_Shi[(size_t)ND_MAX * KDIM];
__device__ __nv_bfloat16 g_Slo[(size_t)ND_MAX * KDIM];
__device__ __nv_bfloat16 g_Bhi[(size_t)COUT * KDIM];
__device__ __nv_bfloat16 g_Blo[(size_t)COUT * KDIM];

// ---------------- common helpers ----------------
template<int N>
__device__ __forceinline__ void layer_norm(float* x, const float* g, const float* be, bool act){
    float s = 0.f;
#pragma unroll
    for (int i = 0; i < N; i++) s += x[i];
    float mu = s * (1.0f / N);
    float v = 0.f;
#pragma unroll
    for (int i = 0; i < N; i++){ float d = x[i] - mu; v += d * d; }
    float inv = rsqrtf(v * (1.0f / N) + 1e-5f);
#pragma unroll
    for (int i = 0; i < N; i++){
        float y = (x[i] - mu) * inv * g[i] + be[i];
        x[i] = act ? (y >= 0.f ? y : 0.1f * y) : y;
    }
}

__device__ __forceinline__ void dense16(const float* w, const float* bvec, const float* in, float* out){
#pragma unroll
    for (int o = 0; o < 16; o++) out[o] = bvec[o];
#pragma unroll
    for (int i = 0; i < 16; i++){
        float hi = in[i];
#pragma unroll
        for (int o4 = 0; o4 < 4; o4++){
            float4 ww = *(const float4*)&w[i*16 + o4*4];
            out[o4*4+0] = fmaf(hi, ww.x, out[o4*4+0]);
            out[o4*4+1] = fmaf(hi, ww.y, out[o4*4+1]);
            out[o4*4+2] = fmaf(hi, ww.z, out[o4*4+2]);
            out[o4*4+3] = fmaf(hi, ww.w, out[o4*4+3]);
        }
    }
}

__device__ __forceinline__ uint32_t s2u(const void* p){
    uint32_t a; asm("{ .reg .u64 t; cvta.to.shared.u64 t, %1; cvt.u32.u64 %0, t; }" : "=r"(a) : "l"(p));
    return a;
}
__device__ __forceinline__ void cpa16(uint32_t dst, const void* src){
    asm volatile("cp.async.cg.shared.global [%0], [%1], 16;" :: "r"(dst), "l"(src));
}

enum {
    PE_W0 = 0,    PE_B0 = 96,   PE_G0 = 128,  PE_BE0 = 160,
    PE_W1 = 192,  PE_B1 = 1216, PE_G1 = 1248, PE_BE1 = 1280,
    WN_W0 = 1312, WN_B0 = 1360, WN_G0 = 1376, WN_BE0 = 1392,
    WN_W1 = 1408, WN_B1 = 1664, WN_G1 = 1680, WN_BE1 = 1696,
    WN_W2 = 1712, WN_B2 = 1968, WN_G2 = 1984, WN_BE2 = 2000,
    P_TOTAL = 2016
};

#define PTS 8

// ===================== Kernel 1 (round-9): gather(cp.async dbuf) + MLPs + einsum =====================
__global__ __launch_bounds__(128)
void k1_weights_einsum(
    const float* __restrict__ sxyz,  const float* __restrict__ sfeat,
    const int*   __restrict__ nei,   const float* __restrict__ dxyz,
    const float* __restrict__ pw0, const float* __restrict__ pb0,
    const float* __restrict__ pg0, const float* __restrict__ pe0,
    const float* __restrict__ pw1, const float* __restrict__ pb1,
    const float* __restrict__ pg1, const float* __restrict__ pe1,
    const float* __restrict__ ww0, const float* __restrict__ wb0,
    const float* __restrict__ wg0, const float* __restrict__ we0,
    const float* __restrict__ ww1, const float* __restrict__ wb1,
    const float* __restrict__ wg1, const float* __restrict__ we1,
    const float* __restrict__ ww2, const float* __restrict__ wb2,
    const float* __restrict__ wg2, const float* __restrict__ we2,
    int Nd)
{
    __shared__ __align__(16) float sp[P_TOTAL];
    __shared__ __align__(16) float pe_s[PTS][KNN][CPE];
    __shared__ __align__(16) float wts_s[PTS][KNN][CM];
    __shared__ __align__(16) float feat_s[2][KNN][132];
    __shared__ int nei_s[PTS][KNN];

    const int t = threadIdx.x;
#define CPY(off, src, n) for (int i = t; i < (n); i += 128) sp[(off)+i] = (src)[i];
    CPY(PE_W0, pw0, 96)   CPY(PE_B0, pb0, 32)  CPY(PE_G0, pg0, 32)  CPY(PE_BE0, pe0, 32)
    CPY(PE_W1, pw1, 1024) CPY(PE_B1, pb1, 32)  CPY(PE_G1, pg1, 32)  CPY(PE_BE1, pe1, 32)
    CPY(WN_W0, ww0, 48)   CPY(WN_B0, wb0, 16)  CPY(WN_G0, wg0, 16)  CPY(WN_BE0, we0, 16)
    CPY(WN_W1, ww1, 256)  CPY(WN_B1, wb1, 16)  CPY(WN_G1, wg1, 16)  CPY(WN_BE1, we1, 16)
    CPY(WN_W2, ww2, 256)  CPY(WN_B2, wb2, 16)  CPY(WN_G2, wg2, 16)  CPY(WN_BE2, we2, 16)
#undef CPY
    __syncthreads();

    const int n0 = blockIdx.x * PTS;

    // ---- phase 1: one (point, neighbor) per thread ----
    {
        const int p = t >> 4, k = t & 15;
        int n = n0 + p; if (n >= Nd) n = Nd - 1;
        const int idx = nei[n * KNN + k];
        nei_s[p][k] = idx;
        const float x0 = sxyz[idx*3+0] - dxyz[n*3+0];
        const float x1 = sxyz[idx*3+1] - dxyz[n*3+1];
        const float x2 = sxyz[idx*3+2] - dxyz[n*3+2];

        float h[32];
#pragma unroll
        for (int o = 0; o < 32; o++)
            h[o] = fmaf(x0, sp[PE_W0+o], fmaf(x1, sp[PE_W0+32+o], fmaf(x2, sp[PE_W0+64+o], sp[PE_B0+o])));
        layer_norm<32>(h, &sp[PE_G0], &sp[PE_BE0], true);

        float h2[32];
#pragma unroll
        for (int o = 0; o < 32; o++) h2[o] = sp[PE_B1+o];
#pragma unroll
        for (int i = 0; i < 32; i++){
            float hi = h[i];
#pragma unroll
            for (int o4 = 0; o4 < 8; o4++){
                float4 ww = *(const float4*)&sp[PE_W1 + i*32 + o4*4];
                h2[o4*4+0] = fmaf(hi, ww.x, h2[o4*4+0]);
                h2[o4*4+1] = fmaf(hi, ww.y, h2[o4*4+1]);
                h2[o4*4+2] = fmaf(hi, ww.z, h2[o4*4+2]);
                h2[o4*4+3] = fmaf(hi, ww.w, h2[o4*4+3]);
            }
        }
        layer_norm<32>(h2, &sp[PE_G1], &sp[PE_BE1], false);
#pragma unroll
        for (int o = 0; o < 32; o++) pe_s[p][k][o] = h2[o];

        float u[16];
#pragma unroll
        for (int o = 0; o < 16; o++)
            u[o] = fmaf(x0, sp[WN_W0+o], fmaf(x1, sp[WN_W0+16+o], fmaf(x2, sp[WN_W0+32+o], sp[WN_B0+o])));
        layer_norm<16>(u, &sp[WN_G0], &sp[WN_BE0], true);
        float u2[16];
        dense16(&sp[WN_W1], &sp[WN_B1], u, u2);
        layer_norm<16>(u2, &sp[WN_G1], &sp[WN_BE1], true);
        float u3[16];
        dense16(&sp[WN_W2], &sp[WN_B2], u2, u3);
        layer_norm<16>(u3, &sp[WN_G2], &sp[WN_BE2], false);
#pragma unroll
        for (int o = 0; o < 16; o++) wts_s[p][k][o] = u3[o];
    }
    __syncthreads();

    // ---- phase 2: cp.async double-buffered gather overlapped with einsum ----
    const int gk = t >> 3, gq = t & 7;
    const uint32_t fbase = s2u(&feat_s[0][0][0]);
    const uint32_t frow  = (uint32_t)(gk * 132 * 4 + gq * 16);
    const uint32_t fbuf  = (uint32_t)(KNN * 132 * 4);

    {
        const float* src = sfeat + (size_t)nei_s[0][gk] * CIN + gq*4;
#pragma unroll
        for (int r = 0; r < 4; r++)
            cpa16(fbase + frow + r*128, src + 32*r);
        asm volatile("cp.async.commit_group;");
    }

    for (int p = 0; p < PTS; p++){
        const int n = n0 + p;
        if (p + 1 < PTS){
            const float* src = sfeat + (size_t)nei_s[p+1][gk] * CIN + gq*4;
            const uint32_t dst = fbase + ((p+1) & 1) * fbuf + frow;
#pragma unroll
            for (int r = 0; r < 4; r++)
                cpa16(dst + r*128, src + 32*r);
            asm volatile("cp.async.commit_group;");
            asm volatile("cp.async.wait_group 1;");
        } else {
            asm volatile("cp.async.wait_group 0;");
        }
        __syncthreads();

        if (n < Nd){
            const int cg = t & 31, mg = t >> 5;
            const float (*fs)[132] = feat_s[p & 1];
            float acc[5][4];
#pragma unroll
            for (int j = 0; j < 5; j++)
#pragma unroll
                for (int i = 0; i < 4; i++) acc[j][i] = 0.f;
#pragma unroll
            for (int k = 0; k < KNN; k++){
                float4 w = *(const float4*)&wts_s[p][k][mg*4];
#pragma unroll
                for (int j = 0; j < 5; j++){
                    float f = (j < 4) ? fs[k][cg + 32*j] : pe_s[p][k][cg];
                    acc[j][0] = fmaf(f, w.x, acc[j][0]);
                    acc[j][1] = fmaf(f, w.y, acc[j][1]);
                    acc[j][2] = fmaf(f, w.z, acc[j][2]);
                    acc[j][3] = fmaf(f, w.w, acc[j][3]);
                }
            }
            __nv_bfloat16* oh = g_Shi + (size_t)n * KDIM;
            __nv_bfloat16* ol = g_Slo + (size_t)n * KDIM;
#pragma unroll
            for (int i = 0; i < 4; i++)
#pragma unroll
                for (int j = 0; j < 5; j++){
                    float x = acc[j][i];
                    int idx = (mg*4 + i)*CF + cg + 32*j;
                    __nv_bfloat16 hi = __float2bfloat16_rn(x);
                    oh[idx] = hi;
                    ol[idx] = __float2bfloat16_rn(x - __bfloat162float(hi));
                }
        }
        __syncthreads();
    }
}

// ===================== prep: permute + split lin_w into B[n][k] =====================
__global__ __launch_bounds__(256)
void kprep(const float* __restrict__ W)
{
    int id = blockIdx.x * 256 + threadIdx.x;
    if (id >= COUT * KDIM) return;
    int n = id / KDIM, k = id - n * KDIM;
    int c = k % CF, m = k / CF;
    float x = W[(long)(c * CM + m) * COUT + n];
    __nv_bfloat16 hi = __float2bfloat16_rn(x);
    g_Bhi[id] = hi;
    g_Blo[id] = __float2bfloat16_rn(x - __bfloat162float(hi));
}

// ===================== Kernel 2: merged single-pass bf16-split GEMM, 4 CTAs/SM =====================
// BM=64, BN=128, BK=32; 128 threads, warp grid 2(m) x 2(n), warp tile 32x64.
// A tiles pad-free at 64B pitch with XOR swizzle: phys = r*64 + ((seg ^ ((r>>1)&3))<<4).
// B tiles at 80B pitch (padded, as before).
#define BK 32
#define NCH (KDIM / BK)        // 80
#define A_BYTES (64 * 64)            // 4096 (64 rows x 64B, swizzled)
#define B_BYTES (128 * 80)           // 10240
// stage layout: [Ahi | Alo | Bh | Bl]
#define OFF_ALO A_BYTES
#define OFF_BH  (2 * A_BYTES)
#define OFF_BL  (2 * A_BYTES + B_BYTES)
#define STG (2 * A_BYTES + 2 * B_BYTES)  // 28672
#define DSMEM (2 * STG)                  // 57344 = 228KB / 4

__device__ __forceinline__ void ldm4(uint32_t* r, uint32_t a){
    asm volatile("ldmatrix.sync.aligned.m8n8.x4.shared.b16 {%0,%1,%2,%3}, [%4];"
        : "=r"(r[0]), "=r"(r[1]), "=r"(r[2]), "=r"(r[3]) : "r"(a));
}
__device__ __forceinline__ void mma16816(float* d, const uint32_t* a, const uint32_t* b){
    asm volatile("mma.sync.aligned.m16n8k16.row.col.f32.bf16.bf16.f32 "
        "{%0,%1,%2,%3}, {%4,%5,%6,%7}, {%8,%9}, {%0,%1,%2,%3};"
        : "+f"(d[0]), "+f"(d[1]), "+f"(d[2]), "+f"(d[3])
        : "r"(a[0]), "r"(a[1]), "r"(a[2]), "r"(a[3]), "r"(b[0]), "r"(b[1]));
}

__device__ __forceinline__ uint32_t a_swz(int row, int seg){
    return (uint32_t)(row * 64 + ((seg ^ ((row >> 1) & 3)) << 4));
}

__device__ __forceinline__ void load_chunk(uint32_t base, int row0, int kb, int t)
{
#pragma unroll
    for (int i = 0; i < 2; i++){
        int f = t + 128*i; int r = f >> 2, sg = f & 3;
        uint32_t d = a_swz(r, sg);
        cpa16(base + d,           g_Shi + (size_t)(row0 + r) * KDIM + kb + sg*8);
        cpa16(base + OFF_ALO + d, g_Slo + (size_t)(row0 + r) * KDIM + kb + sg*8);
    }
#pragma unroll
    for (int i = 0; i < 4; i++){
        int f = t + 128*i; int r = f >> 2, sg = f & 3;
        cpa16(base + OFF_BH + r*80 + sg*16, g_Bhi + (size_t)r * KDIM + kb + sg*8);
        cpa16(base + OFF_BL + r*80 + sg*16, g_Blo + (size_t)r * KDIM + kb + sg*8);
    }
}

__global__ __launch_bounds__(128, 4)
void k2_gemm_ln(const float* __restrict__ lb, const float* __restrict__ lg,
                const float* __restrict__ lbe, const float* __restrict__ dfeat,
                float* __restrict__ out, int Nd)
{
    extern __shared__ __align__(128) char dsm[];

    const int t = threadIdx.x;
    const int w = t >> 5, l = t & 31;
    const int wm = w & 1, wn = w >> 1;
    const int row0 = blockIdx.x * 64;

    const uint32_t smem = s2u(dsm);
    const int grp = l >> 3, lr = l & 7;
    const int aRow = wm*32 + ((grp & 1) << 3) + lr;
    const int aK   = (grp >> 1) << 3;
    const int bRow = wn*64 + ((grp >> 1) << 3) + lr;
    const int bK   = (grp & 1) << 3;

    float acc[2][8][4];
#pragma unroll
    for (int i = 0; i < 2; i++)
#pragma unroll
        for (int j = 0; j < 8; j++)
#pragma unroll
            for (int q = 0; q < 4; q++) acc[i][j][q] = 0.f;

    load_chunk(smem, row0, 0, t);
    asm volatile("cp.async.commit_group;");
    for (int ch = 0; ch < NCH; ch++){
        const uint32_t cur = smem + (ch & 1) * STG;
        if (ch + 1 < NCH){
            load_chunk(smem + ((ch + 1) & 1) * STG, row0, (ch + 1) * BK, t);
            asm volatile("cp.async.commit_group;");
            asm volatile("cp.async.wait_group 1;");
        } else {
            asm volatile("cp.async.wait_group 0;");
        }
        __syncthreads();
#pragma unroll
        for (int s = 0; s < 2; s++){
            uint32_t ah[2][4], al[2][4];
#pragma unroll
            for (int i = 0; i < 2; i++){
                const uint32_t offA = a_swz(aRow + i*16, (s*16 + aK) >> 3);
                ldm4(ah[i], cur + offA);
                ldm4(al[i], cur + OFF_ALO + offA);
            }
            uint32_t bh[4][4], bl[4][4];
#pragma unroll
            for (int j2 = 0; j2 < 4; j2++){
                ldm4(bh[j2], cur + OFF_BH + (uint32_t)((bRow + j2*16)*80 + (s*16 + bK)*2));
                ldm4(bl[j2], cur + OFF_BL + (uint32_t)((bRow + j2*16)*80 + (s*16 + bK)*2));
            }
#pragma unroll
            for (int i = 0; i < 2; i++)
#pragma unroll
                for (int j2 = 0; j2 < 4; j2++){
                    mma16816(acc[i][2*j2],   ah[i], &bh[j2][0]);
                    mma16816(acc[i][2*j2+1], ah[i], &bh[j2][2]);
                    mma16816(acc[i][2*j2],   ah[i], &bl[j2][0]);
                    mma16816(acc[i][2*j2+1], ah[i], &bl[j2][2]);
                    mma16816(acc[i][2*j2],   al[i], &bh[j2][0]);
                    mma16816(acc[i][2*j2+1], al[i], &bh[j2][2]);
                }
        }
        __syncthreads();
    }

    // ---- epilogue: reuse dynamic smem (stages are dead) ----
    float* sm   = (float*)dsm;            // [64][132]
    float* sbp  = sm + 64*132;            // bias   [128]
    float* sgp  = sbp + 128;              // gamma  [128]
    float* sbep = sgp + 128;              // beta   [128]
    float (*red)[2][2] = (float(*)[2][2])(sbep + 128);   // [64][2][2]

    sbp[t] = lb[t]; sgp[t] = lg[t]; sbep[t] = lbe[t];    // 128 threads, 128 values
    __syncthreads();

    const int P = 132;
    const int dr = l >> 2, dc = 2 * (l & 3);
#pragma unroll
    for (int i = 0; i < 2; i++)
#pragma unroll
        for (int j = 0; j < 8; j++){
            int row = wm*32 + i*16 + dr;
            int col = wn*64 + j*8 + dc;
            sm[row*P + col]         = acc[i][j][0] + sbp[col];
            sm[row*P + col + 1]     = acc[i][j][1] + sbp[col + 1];
            sm[(row+8)*P + col]     = acc[i][j][2] + sbp[col];
            sm[(row+8)*P + col + 1] = acc[i][j][3] + sbp[col + 1];
        }
    __syncthreads();

    {   // stats: thread t handles row t>>1, half t&1
        const int r = t >> 1, h = t & 1;
        float s = 0.f, ss = 0.f;
#pragma unroll 16
        for (int c = 0; c < 64; c++){
            float v = sm[r*P + h*64 + c];
            s += v; ss += v * v;
        }
        red[r][h][0] = s; red[r][h][1] = ss;
    }
    __syncthreads();

    // write out: warp w -> rows w*16 .. w*16+15, lane l -> cols l*4..l*4+3
    for (int rr = 0; rr < 16; rr++){
        const int row = w*16 + rr;
        const float S  = red[row][0][0] + red[row][1][0];
        const float SS = red[row][0][1] + red[row][1][1];
        const float mu  = S * (1.0f / 128.0f);
        const float var = SS * (1.0f / 128.0f) - mu * mu;
        const float inv = rsqrtf(var + 1e-5f);
        const int c0 = l * 4;
        float4 d = *(const float4*)&dfeat[(size_t)(row0 + row) * COUT + c0];
        float o[4];
#pragma unroll
        for (int q = 0; q < 4; q++){
            float y = (sm[row*P + c0 + q] - mu) * inv * sgp[c0 + q] + sbep[c0 + q];
            o[q] = (y >= 0.f) ? y : 0.1f * y;
        }
        o[0] += d.x; o[1] += d.y; o[2] += d.z; o[3] += d.w;
        *(float4*)&out[(size_t)(row0 + row) * COUT + c0] = make_float4(o[0], o[1], o[2], o[3]);
    }
}

// ============================================================================
extern "C" void kernel_launch(void* const* d_in, const int* in_sizes, int n_in,
                              void* d_out, int out_size)
{
    const float* sxyz  = (const float*)d_in[0];
    const float* sfeat = (const float*)d_in[1];
    const int*   nei   = (const int*)  d_in[2];
    const float* dxyz  = (const float*)d_in[4];
    const float* dfeat = (const float*)d_in[6];
    const float* pw0 = (const float*)d_in[7],  *pb0 = (const float*)d_in[8];
    const float* pg0 = (const float*)d_in[9],  *pe0 = (const float*)d_in[10];
    const float* pw1 = (const float*)d_in[11], *pb1 = (const float*)d_in[12];
    const float* pg1 = (const float*)d_in[13], *pe1 = (const float*)d_in[14];
    const float* ww0 = (const float*)d_in[15], *wb0 = (const float*)d_in[16];
    const float* wg0 = (const float*)d_in[17], *we0 = (const float*)d_in[18];
    const float* ww1 = (const float*)d_in[19], *wb1 = (const float*)d_in[20];
    const float* wg1 = (const float*)d_in[21], *we1 = (const float*)d_in[22];
    const float* ww2 = (const float*)d_in[23], *wb2 = (const float*)d_in[24];
    const float* wg2 = (const float*)d_in[25], *we2 = (const float*)d_in[26];
    const float* lw  = (const float*)d_in[27], *lb  = (const float*)d_in[28];
    const float* lg  = (const float*)d_in[29], *lbe = (const float*)d_in[30];
    float* out = (float*)d_out;

    const int Nd = in_sizes[4] / 3;   // 40000

    cudaFuncSetAttribute(k2_gemm_ln, cudaFuncAttributeMaxDynamicSharedMemorySize, DSMEM);

    kprep<<<(COUT * KDIM + 255) / 256, 256>>>(lw);

    k1_weights_einsum<<<(Nd + PTS - 1) / PTS, 128>>>(
        sxyz, sfeat, nei, dxyz,
        pw0, pb0, pg0, pe0, pw1, pb1, pg1, pe1,
        ww0, wb0, wg0, we0, ww1, wb1, wg1, we1, ww2, wb2, wg2, we2, Nd);

    k2_gemm_ln<<<(Nd + 63) / 64, 128, DSMEM>>>(lb, lg, lbe, dfeat, out, Nd);
}

// round 13
// speedup vs baseline: 1.1830x; 1.0175x over previous
#include <cuda_runtime.h>
#include <cuda_bf16.h>
#include <cstdint>

typedef unsigned long long ull;

#define KNN 16
#define CIN 128
#define CPE 32
#define CF 160
#define CM 16
#define KDIM 2560
#define COUT 128
#define ND_MAX 40000

// split-bf16 scratch: S[n][k] with k = m*160+c ; B[n][k] = Wperm[k][n]
__device__ __nv_bfloat16 g_Shi[(size_t)ND_MAX * KDIM];
__device__ __nv_bfloat16 g_Slo[(size_t)ND_MAX * KDIM];
__device__ __nv_bfloat16 g_Bhi[(size_t)COUT * KDIM];
__device__ __nv_bfloat16 g_Blo[(size_t)COUT * KDIM];

// ---------------- common helpers ----------------
__device__ __forceinline__ ull fma2(ull a, ull b, ull c){
    ull d; asm("fma.rn.f32x2 %0, %1, %2, %3;" : "=l"(d) : "l"(a), "l"(b), "l"(c)); return d;
}
__device__ __forceinline__ float2 unpack2(ull u){
    unsigned lo, hi; asm("mov.b64 {%0, %1}, %2;" : "=r"(lo), "=r"(hi) : "l"(u));
    return make_float2(__uint_as_float(lo), __uint_as_float(hi));
}
__device__ __forceinline__ ull dup2(float a){
    ull d; unsigned x = __float_as_uint(a);
    asm("mov.b64 %0, {%1, %1};" : "=l"(d) : "r"(x)); return d;
}

template<int N>
__device__ __forceinline__ void layer_norm(float* x, const float* g, const float* be, bool act){
    float s = 0.f;
#pragma unroll
    for (int i = 0; i < N; i++) s += x[i];
    float mu = s * (1.0f / N);
    float v = 0.f;
#pragma unroll
    for (int i = 0; i < N; i++){ float d = x[i] - mu; v += d * d; }
    float inv = rsqrtf(v * (1.0f / N) + 1e-5f);
#pragma unroll
    for (int i = 0; i < N; i++){
        float y = (x[i] - mu) * inv * g[i] + be[i];
        x[i] = act ? (y >= 0.f ? y : 0.1f * y) : y;
    }
}

__device__ __forceinline__ void dense16(const float* w, const float* bvec, const float* in, float* out){
#pragma unroll
    for (int o = 0; o < 16; o++) out[o] = bvec[o];
#pragma unroll
    for (int i = 0; i < 16; i++){
        float hi = in[i];
#pragma unroll
        for (int o4 = 0; o4 < 4; o4++){
            float4 ww = *(const float4*)&w[i*16 + o4*4];
            out[o4*4+0] = fmaf(hi, ww.x, out[o4*4+0]);
            out[o4*4+1] = fmaf(hi, ww.y, out[o4*4+1]);
            out[o4*4+2] = fmaf(hi, ww.z, out[o4*4+2]);
            out[o4*4+3] = fmaf(hi, ww.w, out[o4*4+3]);
        }
    }
}

__device__ __forceinline__ uint32_t s2u(const void* p){
    uint32_t a; asm("{ .reg .u64 t; cvta.to.shared.u64 t, %1; cvt.u32.u64 %0, t; }" : "=r"(a) : "l"(p));
    return a;
}
__device__ __forceinline__ void cpa16(uint32_t dst, const void* src){
    asm volatile("cp.async.cg.shared.global [%0], [%1], 16;" :: "r"(dst), "l"(src));
}

enum {
    PE_W0 = 0,    PE_B0 = 96,   PE_G0 = 128,  PE_BE0 = 160,
    PE_W1 = 192,  PE_B1 = 1216, PE_G1 = 1248, PE_BE1 = 1280,
    WN_W0 = 1312, WN_B0 = 1360, WN_G0 = 1376, WN_BE0 = 1392,
    WN_W1 = 1408, WN_B1 = 1664, WN_G1 = 1680, WN_BE1 = 1696,
    WN_W2 = 1712, WN_B2 = 1968, WN_G2 = 1984, WN_BE2 = 2000,
    P_TOTAL = 2016
};

#define PTS 8

// ===================== Kernel 1: gather(cp.async dbuf) + MLPs + f32x2 einsum =====================
__global__ __launch_bounds__(128)
void k1_weights_einsum(
    const float* __restrict__ sxyz,  const float* __restrict__ sfeat,
    const int*   __restrict__ nei,   const float* __restrict__ dxyz,
    const float* __restrict__ pw0, const float* __restrict__ pb0,
    const float* __restrict__ pg0, const float* __restrict__ pe0,
    const float* __restrict__ pw1, const float* __restrict__ pb1,
    const float* __restrict__ pg1, const float* __restrict__ pe1,
    const float* __restrict__ ww0, const float* __restrict__ wb0,
    const float* __restrict__ wg0, const float* __restrict__ we0,
    const float* __restrict__ ww1, const float* __restrict__ wb1,
    const float* __restrict__ wg1, const float* __restrict__ we1,
    const float* __restrict__ ww2, const float* __restrict__ wb2,
    const float* __restrict__ wg2, const float* __restrict__ we2,
    int Nd)
{
    __shared__ __align__(16) float sp[P_TOTAL];
    __shared__ __align__(16) float pe_s[PTS][KNN][CPE];
    __shared__ __align__(16) float wts_s[PTS][KNN][CM];
    __shared__ __align__(16) float feat_s[2][KNN][132];
    __shared__ int nei_s[PTS][KNN];

    const int t = threadIdx.x;
#define CPY(off, src, n) for (int i = t; i < (n); i += 128) sp[(off)+i] = (src)[i];
    CPY(PE_W0, pw0, 96)   CPY(PE_B0, pb0, 32)  CPY(PE_G0, pg0, 32)  CPY(PE_BE0, pe0, 32)
    CPY(PE_W1, pw1, 1024) CPY(PE_B1, pb1, 32)  CPY(PE_G1, pg1, 32)  CPY(PE_BE1, pe1, 32)
    CPY(WN_W0, ww0, 48)   CPY(WN_B0, wb0, 16)  CPY(WN_G0, wg0, 16)  CPY(WN_BE0, we0, 16)
    CPY(WN_W1, ww1, 256)  CPY(WN_B1, wb1, 16)  CPY(WN_G1, wg1, 16)  CPY(WN_BE1, we1, 16)
    CPY(WN_W2, ww2, 256)  CPY(WN_B2, wb2, 16)  CPY(WN_G2, wg2, 16)  CPY(WN_BE2, we2, 16)
#undef CPY
    __syncthreads();

    const int n0 = blockIdx.x * PTS;

    // ---- phase 1: one (point, neighbor) per thread ----
    {
        const int p = t >> 4, k = t & 15;
        int n = n0 + p; if (n >= Nd) n = Nd - 1;
        const int idx = nei[n * KNN + k];
        nei_s[p][k] = idx;
        const float x0 = sxyz[idx*3+0] - dxyz[n*3+0];
        const float x1 = sxyz[idx*3+1] - dxyz[n*3+1];
        const float x2 = sxyz[idx*3+2] - dxyz[n*3+2];

        float h[32];
#pragma unroll
        for (int o = 0; o < 32; o++)
            h[o] = fmaf(x0, sp[PE_W0+o], fmaf(x1, sp[PE_W0+32+o], fmaf(x2, sp[PE_W0+64+o], sp[PE_B0+o])));
        layer_norm<32>(h, &sp[PE_G0], &sp[PE_BE0], true);

        float h2[32];
#pragma unroll
        for (int o = 0; o < 32; o++) h2[o] = sp[PE_B1+o];
#pragma unroll
        for (int i = 0; i < 32; i++){
            float hi = h[i];
#pragma unroll
            for (int o4 = 0; o4 < 8; o4++){
                float4 ww = *(const float4*)&sp[PE_W1 + i*32 + o4*4];
                h2[o4*4+0] = fmaf(hi, ww.x, h2[o4*4+0]);
                h2[o4*4+1] = fmaf(hi, ww.y, h2[o4*4+1]);
                h2[o4*4+2] = fmaf(hi, ww.z, h2[o4*4+2]);
                h2[o4*4+3] = fmaf(hi, ww.w, h2[o4*4+3]);
            }
        }
        layer_norm<32>(h2, &sp[PE_G1], &sp[PE_BE1], false);
#pragma unroll
        for (int o = 0; o < 32; o++) pe_s[p][k][o] = h2[o];

        float u[16];
#pragma unroll
        for (int o = 0; o < 16; o++)
            u[o] = fmaf(x0, sp[WN_W0+o], fmaf(x1, sp[WN_W0+16+o], fmaf(x2, sp[WN_W0+32+o], sp[WN_B0+o])));
        layer_norm<16>(u, &sp[WN_G0], &sp[WN_BE0], true);
        float u2[16];
        dense16(&sp[WN_W1], &sp[WN_B1], u, u2);
        layer_norm<16>(u2, &sp[WN_G1], &sp[WN_BE1], true);
        float u3[16];
        dense16(&sp[WN_W2], &sp[WN_B2], u2, u3);
        layer_norm<16>(u3, &sp[WN_G2], &sp[WN_BE2], false);
#pragma unroll
        for (int o = 0; o < 16; o++) wts_s[p][k][o] = u3[o];
    }
    __syncthreads();

    // ---- phase 2: cp.async double-buffered gather overlapped with f32x2 einsum ----
    const int gk = t >> 3, gq = t & 7;
    const uint32_t fbase = s2u(&feat_s[0][0][0]);
    const uint32_t frow  = (uint32_t)(gk * 132 * 4 + gq * 16);
    const uint32_t fbuf  = (uint32_t)(KNN * 132 * 4);

    {
        const float* src = sfeat + (size_t)nei_s[0][gk] * CIN + gq*4;
#pragma unroll
        for (int r = 0; r < 4; r++)
            cpa16(fbase + frow + r*128, src + 32*r);
        asm volatile("cp.async.commit_group;");
    }

    for (int p = 0; p < PTS; p++){
        const int n = n0 + p;
        if (p + 1 < PTS){
            const float* src = sfeat + (size_t)nei_s[p+1][gk] * CIN + gq*4;
            const uint32_t dst = fbase + ((p+1) & 1) * fbuf + frow;
#pragma unroll
            for (int r = 0; r < 4; r++)
                cpa16(dst + r*128, src + 32*r);
            asm volatile("cp.async.commit_group;");
            asm volatile("cp.async.wait_group 1;");
        } else {
            asm volatile("cp.async.wait_group 0;");
        }
        __syncthreads();

        if (n < Nd){
            const int cg = t & 31, mg = t >> 5;
            const float (*fs)[132] = feat_s[p & 1];
            ull acc2[5][2];
#pragma unroll
            for (int j = 0; j < 5; j++){ acc2[j][0] = 0ULL; acc2[j][1] = 0ULL; }
#pragma unroll
            for (int k = 0; k < KNN; k++){
                const ull* wp = (const ull*)&wts_s[p][k][mg*4];   // 16B aligned
                ull w01 = wp[0], w23 = wp[1];
#pragma unroll
                for (int j = 0; j < 5; j++){
                    float f = (j < 4) ? fs[k][cg + 32*j] : pe_s[p][k][cg];
                    ull fd = dup2(f);
                    acc2[j][0] = fma2(fd, w01, acc2[j][0]);
                    acc2[j][1] = fma2(fd, w23, acc2[j][1]);
                }
            }
            __nv_bfloat16* oh = g_Shi + (size_t)n * KDIM;
            __nv_bfloat16* ol = g_Slo + (size_t)n * KDIM;
#pragma unroll
            for (int h = 0; h < 2; h++)
#pragma unroll
                for (int j = 0; j < 5; j++){
                    float2 v = unpack2(acc2[j][h]);
                    const int m0 = mg*4 + 2*h;
                    const int idx0 = m0*CF + cg + 32*j;
                    __nv_bfloat16 h0 = __float2bfloat16_rn(v.x);
                    oh[idx0] = h0;
                    ol[idx0] = __float2bfloat16_rn(v.x - __bfloat162float(h0));
                    __nv_bfloat16 h1 = __float2bfloat16_rn(v.y);
                    oh[idx0 + CF] = h1;
                    ol[idx0 + CF] = __float2bfloat16_rn(v.y - __bfloat162float(h1));
                }
        }
        __syncthreads();
    }
}

// ===================== prep: permute + split lin_w into B[n][k] =====================
__global__ __launch_bounds__(256)
void kprep(const float* __restrict__ W)
{
    int id = blockIdx.x * 256 + threadIdx.x;
    if (id >= COUT * KDIM) return;
    int n = id / KDIM, k = id - n * KDIM;
    int c = k % CF, m = k / CF;
    float x = W[(long)(c * CM + m) * COUT + n];
    __nv_bfloat16 hi = __float2bfloat16_rn(x);
    g_Bhi[id] = hi;
    g_Blo[id] = __float2bfloat16_rn(x - __bfloat162float(hi));
}

// ===================== Kernel 2 (round-12): merged single-pass bf16-split GEMM, 4 CTAs/SM =====================
#define BK 32
#define NCH (KDIM / BK)        // 80
#define A_BYTES (64 * 64)            // 4096 (64 rows x 64B, swizzled)
#define B_BYTES (128 * 80)           // 10240
#define OFF_ALO A_BYTES
#define OFF_BH  (2 * A_BYTES)
#define OFF_BL  (2 * A_BYTES + B_BYTES)
#define STG (2 * A_BYTES + 2 * B_BYTES)  // 28672
#define DSMEM (2 * STG)                  // 57344

__device__ __forceinline__ void ldm4(uint32_t* r, uint32_t a){
    asm volatile("ldmatrix.sync.aligned.m8n8.x4.shared.b16 {%0,%1,%2,%3}, [%4];"
        : "=r"(r[0]), "=r"(r[1]), "=r"(r[2]), "=r"(r[3]) : "r"(a));
}
__device__ __forceinline__ void mma16816(float* d, const uint32_t* a, const uint32_t* b){
    asm volatile("mma.sync.aligned.m16n8k16.row.col.f32.bf16.bf16.f32 "
        "{%0,%1,%2,%3}, {%4,%5,%6,%7}, {%8,%9}, {%0,%1,%2,%3};"
        : "+f"(d[0]), "+f"(d[1]), "+f"(d[2]), "+f"(d[3])
        : "r"(a[0]), "r"(a[1]), "r"(a[2]), "r"(a[3]), "r"(b[0]), "r"(b[1]));
}

__device__ __forceinline__ uint32_t a_swz(int row, int seg){
    return (uint32_t)(row * 64 + ((seg ^ ((row >> 1) & 3)) << 4));
}

__device__ __forceinline__ void load_chunk(uint32_t base, int row0, int kb, int t)
{
#pragma unroll
    for (int i = 0; i < 2; i++){
        int f = t + 128*i; int r = f >> 2, sg = f & 3;
        uint32_t d = a_swz(r, sg);
        cpa16(base + d,           g_Shi + (size_t)(row0 + r) * KDIM + kb + sg*8);
        cpa16(base + OFF_ALO + d, g_Slo + (size_t)(row0 + r) * KDIM + kb + sg*8);
    }
#pragma unroll
    for (int i = 0; i < 4; i++){
        int f = t + 128*i; int r = f >> 2, sg = f & 3;
        cpa16(base + OFF_BH + r*80 + sg*16, g_Bhi + (size_t)r * KDIM + kb + sg*8);
        cpa16(base + OFF_BL + r*80 + sg*16, g_Blo + (size_t)r * KDIM + kb + sg*8);
    }
}

__global__ __launch_bounds__(128, 4)
void k2_gemm_ln(const float* __restrict__ lb, const float* __restrict__ lg,
                const float* __restrict__ lbe, const float* __restrict__ dfeat,
                float* __restrict__ out, int Nd)
{
    extern __shared__ __align__(128) char dsm[];

    const int t = threadIdx.x;
    const int w = t >> 5, l = t & 31;
    const int wm = w & 1, wn = w >> 1;
    const int row0 = blockIdx.x * 64;

    const uint32_t smem = s2u(dsm);
    const int grp = l >> 3, lr = l & 7;
    const int aRow = wm*32 + ((grp & 1) << 3) + lr;
    const int aK   = (grp >> 1) << 3;
    const int bRow = wn*64 + ((grp >> 1) << 3) + lr;
    const int bK   = (grp & 1) << 3;

    float acc[2][8][4];
#pragma unroll
    for (int i = 0; i < 2; i++)
#pragma unroll
        for (int j = 0; j < 8; j++)
#pragma unroll
            for (int q = 0; q < 4; q++) acc[i][j][q] = 0.f;

    load_chunk(smem, row0, 0, t);
    asm volatile("cp.async.commit_group;");
    for (int ch = 0; ch < NCH; ch++){
        const uint32_t cur = smem + (ch & 1) * STG;
        if (ch + 1 < NCH){
            load_chunk(smem + ((ch + 1) & 1) * STG, row0, (ch + 1) * BK, t);
            asm volatile("cp.async.commit_group;");
            asm volatile("cp.async.wait_group 1;");
        } else {
            asm volatile("cp.async.wait_group 0;");
        }
        __syncthreads();
#pragma unroll
        for (int s = 0; s < 2; s++){
            uint32_t ah[2][4], al[2][4];
#pragma unroll
            for (int i = 0; i < 2; i++){
                const uint32_t offA = a_swz(aRow + i*16, (s*16 + aK) >> 3);
                ldm4(ah[i], cur + offA);
                ldm4(al[i], cur + OFF_ALO + offA);
            }
            uint32_t bh[4][4], bl[4][4];
#pragma unroll
            for (int j2 = 0; j2 < 4; j2++){
                ldm4(bh[j2], cur + OFF_BH + (uint32_t)((bRow + j2*16)*80 + (s*16 + bK)*2));
                ldm4(bl[j2], cur + OFF_BL + (uint32_t)((bRow + j2*16)*80 + (s*16 + bK)*2));
            }
#pragma unroll
            for (int i = 0; i < 2; i++)
#pragma unroll
                for (int j2 = 0; j2 < 4; j2++){
                    mma16816(acc[i][2*j2],   ah[i], &bh[j2][0]);
                    mma16816(acc[i][2*j2+1], ah[i], &bh[j2][2]);
                    mma16816(acc[i][2*j2],   ah[i], &bl[j2][0]);
                    mma16816(acc[i][2*j2+1], ah[i], &bl[j2][2]);
                    mma16816(acc[i][2*j2],   al[i], &bh[j2][0]);
                    mma16816(acc[i][2*j2+1], al[i], &bh[j2][2]);
                }
        }
        __syncthreads();
    }

    // ---- epilogue: reuse dynamic smem (stages are dead) ----
    float* sm   = (float*)dsm;            // [64][132]
    float* sbp  = sm + 64*132;            // bias   [128]
    float* sgp  = sbp + 128;              // gamma  [128]
    float* sbep = sgp + 128;              // beta   [128]
    float (*red)[2][2] = (float(*)[2][2])(sbep + 128);   // [64][2][2]

    sbp[t] = lb[t]; sgp[t] = lg[t]; sbep[t] = lbe[t];
    __syncthreads();

    const int P = 132;
    const int dr = l >> 2, dc = 2 * (l & 3);
#pragma unroll
    for (int i = 0; i < 2; i++)
#pragma unroll
        for (int j = 0; j < 8; j++){
            int row = wm*32 + i*16 + dr;
            int col = wn*64 + j*8 + dc;
            sm[row*P + col]         = acc[i][j][0] + sbp[col];
            sm[row*P + col + 1]     = acc[i][j][1] + sbp[col + 1];
            sm[(row+8)*P + col]     = acc[i][j][2] + sbp[col];
            sm[(row+8)*P + col + 1] = acc[i][j][3] + sbp[col + 1];
        }
    __syncthreads();

    {
        const int r = t >> 1, h = t & 1;
        float s = 0.f, ss = 0.f;
#pragma unroll 16
        for (int c = 0; c < 64; c++){
            float v = sm[r*P + h*64 + c];
            s += v; ss += v * v;
        }
        red[r][h][0] = s; red[r][h][1] = ss;
    }
    __syncthreads();

    for (int rr = 0; rr < 16; rr++){
        const int row = w*16 + rr;
        const float S  = red[row][0][0] + red[row][1][0];
        const float SS = red[row][0][1] + red[row][1][1];
        const float mu  = S * (1.0f / 128.0f);
        const float var = SS * (1.0f / 128.0f) - mu * mu;
        const float inv = rsqrtf(var + 1e-5f);
        const int c0 = l * 4;
        float4 d = *(const float4*)&dfeat[(size_t)(row0 + row) * COUT + c0];
        float o[4];
#pragma unroll
        for (int q = 0; q < 4; q++){
            float y = (sm[row*P + c0 + q] - mu) * inv * sgp[c0 + q] + sbep[c0 + q];
            o[q] = (y >= 0.f) ? y : 0.1f * y;
        }
        o[0] += d.x; o[1] += d.y; o[2] += d.z; o[3] += d.w;
        *(float4*)&out[(size_t)(row0 + row) * COUT + c0] = make_float4(o[0], o[1], o[2], o[3]);
    }
}

// ============================================================================
extern "C" void kernel_launch(void* const* d_in, const int* in_sizes, int n_in,
                              void* d_out, int out_size)
{
    const float* sxyz  = (const float*)d_in[0];
    const float* sfeat = (const float*)d_in[1];
    const int*   nei   = (const int*)  d_in[2];
    const float* dxyz  = (const float*)d_in[4];
    const float* dfeat = (const float*)d_in[6];
    const float* pw0 = (const float*)d_in[7],  *pb0 = (const float*)d_in[8];
    const float* pg0 = (const float*)d_in[9],  *pe0 = (const float*)d_in[10];
    const float* pw1 = (const float*)d_in[11], *pb1 = (const float*)d_in[12];
    const float* pg1 = (const float*)d_in[13], *pe1 = (const float*)d_in[14];
    const float* ww0 = (const float*)d_in[15], *wb0 = (const float*)d_in[16];
    const float* wg0 = (const float*)d_in[17], *we0 = (const float*)d_in[18];
    const float* ww1 = (const float*)d_in[19], *wb1 = (const float*)d_in[20];
    const float* wg1 = (const float*)d_in[21], *we1 = (const float*)d_in[22];
    const float* ww2 = (const float*)d_in[23], *wb2 = (const float*)d_in[24];
    const float* wg2 = (const float*)d_in[25], *we2 = (const float*)d_in[26];
    const float* lw  = (const float*)d_in[27], *lb  = (const float*)d_in[28];
    const float* lg  = (const float*)d_in[29], *lbe = (const float*)d_in[30];
    float* out = (float*)d_out;

    const int Nd = in_sizes[4] / 3;   // 40000

    cudaFuncSetAttribute(k2_gemm_ln, cudaFuncAttributeMaxDynamicSharedMemorySize, DSMEM);

    kprep<<<(COUT * KDIM + 255) / 256, 256>>>(lw);

    k1_weights_einsum<<<(Nd + PTS - 1) / PTS, 128>>>(
        sxyz, sfeat, nei, dxyz,
        pw0, pb0, pg0, pe0, pw1, pb1, pg1, pe1,
        ww0, wb0, wg0, we0, ww1, wb1, wg1, we1, ww2, wb2, wg2, we2, Nd);

    k2_gemm_ln<<<(Nd + 63) / 64, 128, DSMEM>>>(lb, lg, lbe, dfeat, out, Nd);
}